// round 14
// baseline (speedup 1.0000x reference)
#include <cuda_runtime.h>
#include <cuda_bf16.h>

#define FULLMASK 0xffffffffu
#define TT 4096

// ---- device scratch (allocation-free) ----
__device__ float g_sum[32][32];     // per-K1-block feature column sums
__device__ float g_cov[32][1024];   // per-K1-block E[f_i f_j] partial sums (full 32x32)
__device__ float g_p2[16][16];      // per-K2-block h2 sum[8] + sumsq[8]
__device__ float g_h2[2048 * 8];

// ============ K1: feature sums + covariance partials (32 x 256; 64 rows/block) ============
__global__ __launch_bounds__(256) void k_cov(const float* __restrict__ features) {
    __shared__ float s_f[64][33];
    __shared__ float s_ps[8][32];
    const int t = threadIdx.x;
    const float* fb = features + (size_t)blockIdx.x * 64 * 32;

    float ps = 0.f;
    #pragma unroll
    for (int k = 0; k < 8; k++) {
        const int gl = k * 256 + t;
        const float v = fb[gl];
        s_f[gl >> 5][gl & 31] = v;
        ps += v;
    }
    s_ps[t >> 5][t & 31] = ps;     // thread covered rows {t>>5 + 8k}, col t&31
    __syncthreads();
    if (t < 32) {
        float a = 0.f;
        #pragma unroll
        for (int w = 0; w < 8; w++) a += s_ps[w][t];
        g_sum[blockIdx.x][t] = a;
    }
    // products: thread -> i = t>>3, j in {jg, jg+8, jg+16, jg+24}
    const int i = t >> 3, jg = t & 7;
    float a0 = 0.f, a1 = 0.f, a2 = 0.f, a3 = 0.f;
    #pragma unroll 8
    for (int r = 0; r < 64; r++) {
        const float fi = s_f[r][i];
        a0 = fmaf(fi, s_f[r][jg],      a0);
        a1 = fmaf(fi, s_f[r][jg + 8],  a1);
        a2 = fmaf(fi, s_f[r][jg + 16], a2);
        a3 = fmaf(fi, s_f[r][jg + 24], a3);
    }
    float* cv = g_cov[blockIdx.x] + i * 32 + jg;
    cv[0] = a0; cv[8] = a1; cv[16] = a2; cv[24] = a3;
}

// ============ K2: analytic bn0/bn1 -> z1 -> h2 (+ h2 stats partials) (16 x 128) ============
__global__ __launch_bounds__(128) void k_mlp(
    const float* __restrict__ features,
    const float* __restrict__ bn0_g, const float* __restrict__ bn0_b,
    const float* __restrict__ W1,    const float* __restrict__ b1,
    const float* __restrict__ bn1_g, const float* __restrict__ bn1_b,
    const float* __restrict__ W2,    const float* __restrict__ b2)
{
    __shared__ float sP[32][33];          // reduced E-products (raw sums)
    __shared__ float sMu[32];
    __shared__ float sSc0[32], sSh0[32];
    __shared__ float sA[8][32];           // A~ = W1 * diag(sc0)
    __shared__ float sCt[8], sS[8];       // c~, S_j = A~_j . mu
    __shared__ float sVar[8];
    __shared__ float sB[8][32];           // B~ = diag(sc1) * A~
    __shared__ float sD[8];               // d~
    __shared__ float sSc1[8];
    __shared__ float sW2[64], sb2v[8];
    __shared__ float s_f2[128][33];
    __shared__ float s_pp[4][16];

    const int t = threadIdx.x, warp = t >> 5, lane = t & 31;

    // stage this block's 128 feature rows (coalesced)
    const float* fb = features + (size_t)blockIdx.x * 128 * 32;
    #pragma unroll
    for (int k = 0; k < 32; k++) {
        const int gl = k * 128 + t;
        s_f2[gl >> 5][gl & 31] = fb[gl];
    }
    // reduce column sums -> mean
    if (t < 32) {
        float a = 0.f;
        #pragma unroll
        for (int b = 0; b < 32; b++) a += g_sum[b][t];
        sMu[t] = a * (1.f / 2048.f);
    }
    // reduce covariance partials
    #pragma unroll
    for (int k = 0; k < 8; k++) {
        const int e = k * 128 + t;
        float a = 0.f;
        #pragma unroll 8
        for (int b = 0; b < 32; b++) a += g_cov[b][e];
        sP[e >> 5][e & 31] = a;
    }
    if (t < 64) sW2[t] = W2[t];
    else if (t < 72) sb2v[t - 64] = b2[t - 64];
    __syncthreads();

    // bn0 affine
    if (t < 32) {
        const float mu = sMu[t];
        const float var = sP[t][t] * (1.f / 2048.f) - mu * mu;
        const float sc = bn0_g[t] * rsqrtf(var + 1e-5f);
        sSc0[t] = sc;
        sSh0[t] = bn0_b[t] - mu * sc;
    }
    __syncthreads();

    // A~ (2 entries per thread)
    {
        const int e0 = t, e1 = t + 128;
        sA[e0 >> 5][e0 & 31] = __ldg(W1 + e0) * sSc0[e0 & 31];
        sA[e1 >> 5][e1 & 31] = __ldg(W1 + e1) * sSc0[e1 & 31];
    }
    __syncthreads();
    if (t < 8) {
        float ct = __ldg(b1 + t), S = 0.f;
        #pragma unroll
        for (int c = 0; c < 32; c++) {
            ct = fmaf(__ldg(W1 + t * 32 + c), sSh0[c], ct);
            S  = fmaf(sA[t][c], sMu[c], S);
        }
        sCt[t] = ct; sS[t] = S;
    }
    __syncthreads();

    // var(h1)_j = (A~_j P A~_j^T)/2048 - S_j^2   (16 partial threads per j)
    {
        const int j = t >> 4, ch = t & 15;
        const int d0 = 2 * ch, d1 = 2 * ch + 1;
        float t0 = 0.f, t1 = 0.f;
        #pragma unroll
        for (int c = 0; c < 32; c++) {
            t0 = fmaf(sA[j][c], sP[c][d0], t0);
            t1 = fmaf(sA[j][c], sP[c][d1], t1);
        }
        float acc = sA[j][d0] * t0 + sA[j][d1] * t1;
        #pragma unroll
        for (int d = 1; d < 16; d <<= 1) acc += __shfl_xor_sync(FULLMASK, acc, d);
        if (ch == 0) sVar[j] = acc * (1.f / 2048.f) - sS[j] * sS[j];
    }
    __syncthreads();
    if (t < 8) {
        const float sc1 = bn1_g[t] * rsqrtf(sVar[t] + 1e-5f);
        sSc1[t] = sc1;
        sD[t] = bn1_b[t] - sc1 * sS[t];   // z1 = relu(sc1*(A~f + c~) + bn1b - sc1*(S+c~)) = relu(sc1*A~ f + bn1b - sc1*S)
    }
    __syncthreads();
    {
        const int e0 = t, e1 = t + 128;
        sB[e0 >> 5][e0 & 31] = sSc1[e0 >> 5] * sA[e0 >> 5][e0 & 31];
        sB[e1 >> 5][e1 & 31] = sSc1[e1 >> 5] * sA[e1 >> 5][e1 & 31];
    }
    __syncthreads();

    // per-row: z1 = relu(B~ f + d~), h2 = W2 z1 + b2
    float z[8], h[8];
    #pragma unroll
    for (int j = 0; j < 8; j++) {
        float a = sD[j];
        #pragma unroll
        for (int c = 0; c < 32; c++) a = fmaf(sB[j][c], s_f2[t][c], a);
        z[j] = fmaxf(a, 0.f);
    }
    #pragma unroll
    for (int k = 0; k < 8; k++) {
        float a = sb2v[k];
        #pragma unroll
        for (int j = 0; j < 8; j++) a = fmaf(sW2[k * 8 + j], z[j], a);
        h[k] = a;
    }
    const int row = blockIdx.x * 128 + t;
    float4* op = (float4*)(g_h2 + row * 8);
    op[0] = make_float4(h[0], h[1], h[2], h[3]);
    op[1] = make_float4(h[4], h[5], h[6], h[7]);

    float sv[16];
    #pragma unroll
    for (int j = 0; j < 8; j++) { sv[j] = h[j]; sv[8 + j] = h[j] * h[j]; }
    #pragma unroll
    for (int d = 16; d; d >>= 1) {
        #pragma unroll
        for (int j = 0; j < 16; j++) sv[j] += __shfl_xor_sync(FULLMASK, sv[j], d);
    }
    if (lane < 16) s_pp[warp][lane] = sv[lane];
    __syncthreads();
    if (t < 16)
        g_p2[blockIdx.x][t] = s_pp[0][t] + s_pp[1][t] + s_pp[2][t] + s_pp[3][t];
}

// ============ K3: per-warp params preamble + R10 scan (256 x 256) ============
// One warp per row; lanes 0-7 finalize bn2 & compute z; lanes 0-5 the sigmoid
// heads; shuffles broadcast params. Then lane l scans steps [128l, 128l+128)
// in closed affine form; 5-round shfl scan composes; butterfly reduce finishes.
__global__ __launch_bounds__(256) void k_scan(const float* __restrict__ X,
                                              const float* __restrict__ Fp,
                                              const float* __restrict__ bn2_g,
                                              const float* __restrict__ bn2_b,
                                              const float* __restrict__ W3,
                                              const float* __restrict__ b3,
                                              const float* __restrict__ pn,
                                              float* __restrict__ out) {
    const int warp = threadIdx.x >> 5, lane = threadIdx.x & 31;
    const int row = blockIdx.x * 8 + warp;
    const float cc = 0.16228221f * __ldg(Fp);   // sqrt(2^(1/3)-1)*F/pi

    // ---- per-warp params (no block sync) ----
    float zj = 0.f;
    if (lane < 8) {
        float ss = 0.f, qq = 0.f;
        #pragma unroll
        for (int b = 0; b < 16; b++) { ss += g_p2[b][lane]; qq += g_p2[b][8 + lane]; }
        const float mean = ss * (1.f / 2048.f);
        const float var  = qq * (1.f / 2048.f) - mean * mean;
        const float sc2  = __ldg(bn2_g + lane) * rsqrtf(var + 1e-5f);
        const float sh2  = __ldg(bn2_b + lane) - mean * sc2;
        zj = fmaxf(fmaf(g_h2[row * 8 + lane], sc2, sh2), 0.f);
    }
    float zz[8];
    #pragma unroll
    for (int k = 0; k < 8; k++) zz[k] = __shfl_sync(FULLMASK, zj, k);
    float sgj = 0.f;
    if (lane < 6) {
        float a = __ldg(b3 + lane) + __ldg(pn + lane);
        #pragma unroll
        for (int k = 0; k < 8; k++) a = fmaf(__ldg(W3 + lane * 8 + k), zz[k], a);
        sgj = __fdividef(1.f, 1.f + __expf(-a));
    }
    const float sg0 = __shfl_sync(FULLMASK, sgj, 0);
    const float sg1 = __shfl_sync(FULLMASK, sgj, 1);
    const float sg2 = __shfl_sync(FULLMASK, sgj, 2);
    const float sg3 = __shfl_sync(FULLMASK, sgj, 3);
    const float sg4 = __shfl_sync(FULLMASK, sgj, 4);
    const float sg5 = __shfl_sync(FULLMASK, sgj, 5);

    const float f_start = fmaf(4.5f,  sg0, 0.5f);
    const float f_inf   = fmaf(0.49f, sg1, 0.01f);
    const float f_decay = 2.f * sg2;
    const float f_T     = 2.f * sg3;
    const float w_off   = sg4;
    const float w_T     = fmaf(0.49f, sg5, 0.01f);

    const float df  = f_start - f_inf;
    const float lnD = fmaf(-2.30258509f, f_decay, -0.35667494f);  // ln(0.7*0.1^fd)
    const float H   = 10.f * __expf(-2.30258509f * f_T);          // 10*0.1^fT
    const float kf  = __fdividef(lnD, 4096.f * H);
    const float G   = __expf(kf);
    const float z0  = __fdividef(w_off, w_T);
    const float lw  = -__fdividef(1.f, 4096.f * w_T);
    const float R   = __expf(lw);

    // ---- scan (R10 body, verbatim) ----
    const float* xrow = X + (size_t)row * TT;
    const int t0 = lane << 7;
    float g = __expf(kf * (float)t0);
    float e = __expf(fmaf(lw, (float)t0, z0));  // may be inf -> w = 0 (correct)
    float xp = xrow[t0 ? t0 - 1 : 0];

    float p = 1.f, r = 0.f, q1 = 0.f, q2 = 0.f;
    float a1 = 0.f, a2 = 0.f, bt = 0.f, ws = 0.f;

    const float4* xv = (const float4*)(xrow + t0);
    float4 v = __ldcs(xv);
    const float y0 = __shfl_sync(FULLMASK, v.x, 0);

#define STEP(xval) do {                               \
    float w_ = __fdividef(1.f, 1.f + e);              \
    float f_ = fmaf(df, g, f_inf);                    \
    float i_ = __fdividef(1.f, cc + f_);              \
    float b_ = f_ * i_;                               \
    float ap = fmaf(-2.f, b_, 1.f);                   \
    g *= G; e *= R;                                   \
    float m_ = fmaf(b_, ap, b_);                      \
    float xx = (xval) + xp;                           \
    float u1 = b_ * xx;                               \
    float u2 = b_ * u1;                               \
    float pm = m_ * p;                                \
    float t2 = fmaf(m_, q1, u2);                      \
    p = ap * p;                                       \
    r = fmaf(ap, r, pm);                              \
    q1 = fmaf(ap, q1, u1);                            \
    q2 = fmaf(ap, q2, t2);                            \
    a1 = fmaf(w_, r, a1);                             \
    a2 = fmaf(w_, p, a2);                             \
    bt = fmaf(w_, q2, bt);                            \
    ws += w_;                                         \
    xp = (xval);                                      \
  } while (0)

    if (lane == 0) {
        // t = 0: y2_0 = y0 passes through identity -> a2 += w0, ws += w0
        float w0 = __fdividef(1.f, 1.f + e);
        a2 = w0; ws = w0;
        g *= G; e *= R;
        // xp stays X[0] for the t=1 step
    } else {
        STEP(v.x);
    }
    STEP(v.y); STEP(v.z); STEP(v.w);
    #pragma unroll 2
    for (int i = 1; i < 32; i++) {
        v = __ldcs(xv + i);
        STEP(v.x); STEP(v.y); STEP(v.z); STEP(v.w);
    }
#undef STEP

    // inclusive scan: compose self with prefix from lower lanes
    #pragma unroll
    for (int d = 1; d < 32; d <<= 1) {
        float pL  = __shfl_up_sync(FULLMASK, p,  d);
        float rL  = __shfl_up_sync(FULLMASK, r,  d);
        float q1L = __shfl_up_sync(FULLMASK, q1, d);
        float q2L = __shfl_up_sync(FULLMASK, q2, d);
        if (lane >= d) {
            float pn2 = p * pL;
            float rn  = fmaf(r, pL, p * rL);
            float q1n = fmaf(p, q1L, q1);
            float q2n = fmaf(r, q1L, fmaf(p, q2L, q2));
            p = pn2; r = rn; q1 = q1n; q2 = q2n;
        }
    }
    // exclusive shift (identity into lane 0)
    float pe  = __shfl_up_sync(FULLMASK, p,  1);
    float re  = __shfl_up_sync(FULLMASK, r,  1);
    float q1e = __shfl_up_sync(FULLMASK, q1, 1);
    float q2e = __shfl_up_sync(FULLMASK, q2, 1);
    if (lane == 0) { pe = 1.f; re = 0.f; q1e = 0.f; q2e = 0.f; }

    const float y1i = fmaf(pe, y0, q1e);
    const float y2i = fmaf(re + pe, y0, q2e);
    float contrib = fmaf(a1, y1i, fmaf(a2, y2i, bt));

    #pragma unroll
    for (int d = 16; d; d >>= 1) {
        contrib += __shfl_xor_sync(FULLMASK, contrib, d);
        ws      += __shfl_xor_sync(FULLMASK, ws, d);
    }
    if (lane == 0) out[row] = contrib / ws;
}

extern "C" void kernel_launch(void* const* d_in, const int* in_sizes, int n_in,
                              void* d_out, int out_size) {
    const float* X        = (const float*)d_in[0];
    const float* features = (const float*)d_in[1];
    const float* F        = (const float*)d_in[2];
    const float* bn0_g    = (const float*)d_in[3];
    const float* bn0_b    = (const float*)d_in[4];
    const float* W1       = (const float*)d_in[5];
    const float* b1       = (const float*)d_in[6];
    const float* bn1_g    = (const float*)d_in[7];
    const float* bn1_b    = (const float*)d_in[8];
    const float* W2       = (const float*)d_in[9];
    const float* b2       = (const float*)d_in[10];
    const float* bn2_g    = (const float*)d_in[11];
    const float* bn2_b    = (const float*)d_in[12];
    const float* W3       = (const float*)d_in[13];
    const float* b3       = (const float*)d_in[14];
    const float* pn       = (const float*)d_in[15];
    float* out = (float*)d_out;

    k_cov<<<32, 256>>>(features);
    k_mlp<<<16, 128>>>(features, bn0_g, bn0_b, W1, b1, bn1_g, bn1_b, W2, b2);
    k_scan<<<256, 256>>>(X, F, bn2_g, bn2_b, W3, b3, pn, out);
}

// round 15
// speedup vs baseline: 1.3054x; 1.3054x over previous
#include <cuda_runtime.h>
#include <cuda_bf16.h>

#define FULLMASK 0xffffffffu
#define TT 4096

// ---- device scratch (allocation-free) ----
__device__ float g_p1[16][16];    // per-block h1 sum[8] + sumsq[8]
__device__ float g_p2[16][16];    // per-block h2 sum[8] + sumsq[8]
__device__ float g_h1[2048 * 8];
__device__ float g_h2[2048 * 8];

// ============ K1: redundant bn0 stats + h1 + bn1 partials (16 x 256) ============
// Each block reads ALL features (L2-broadcast across the 16 concurrent blocks)
// and computes bn0 column stats itself -> no stats kernel, no partial round-trip.
__global__ __launch_bounds__(256) void k_h1(const float* __restrict__ features,
                                            const float* __restrict__ bn0_g,
                                            const float* __restrict__ bn0_b,
                                            const float* __restrict__ W1,
                                            const float* __restrict__ b1) {
    __shared__ float red[8][64];
    __shared__ float s_sc0[32], s_sh0[32];
    __shared__ float s_f[128][33];
    __shared__ float sW1[256], sb1[8];
    __shared__ float s_p[4][16];

    const int t = threadIdx.x, warp = t >> 5, lane = t & 31;

    // ---- full-batch column stats (every block, redundantly) ----
    // float4 index i = k*256 + t; its column group is (t & 7) * 4 (const per thread).
    const float4* fp = (const float4*)features;   // 16384 float4
    float s0 = 0.f, s1 = 0.f, s2 = 0.f, s3 = 0.f;
    float q0 = 0.f, q1 = 0.f, q2 = 0.f, q3 = 0.f;
    #pragma unroll 8
    for (int k = 0; k < 64; k++) {
        const float4 v = __ldg(fp + k * 256 + t);
        s0 += v.x; s1 += v.y; s2 += v.z; s3 += v.w;
        q0 = fmaf(v.x, v.x, q0); q1 = fmaf(v.y, v.y, q1);
        q2 = fmaf(v.z, v.z, q2); q3 = fmaf(v.w, v.w, q3);
    }
    #pragma unroll
    for (int d = 8; d <= 16; d <<= 1) {
        s0 += __shfl_xor_sync(FULLMASK, s0, d); s1 += __shfl_xor_sync(FULLMASK, s1, d);
        s2 += __shfl_xor_sync(FULLMASK, s2, d); s3 += __shfl_xor_sync(FULLMASK, s3, d);
        q0 += __shfl_xor_sync(FULLMASK, q0, d); q1 += __shfl_xor_sync(FULLMASK, q1, d);
        q2 += __shfl_xor_sync(FULLMASK, q2, d); q3 += __shfl_xor_sync(FULLMASK, q3, d);
    }
    if (lane < 8) {
        const int c = lane * 4;
        red[warp][c + 0] = s0; red[warp][c + 1] = s1;
        red[warp][c + 2] = s2; red[warp][c + 3] = s3;
        red[warp][32 + c + 0] = q0; red[warp][32 + c + 1] = q1;
        red[warp][32 + c + 2] = q2; red[warp][32 + c + 3] = q3;
    }
    // stage weights + own rows while stats land
    if (t < 256) sW1[t] = W1[t];
    if (t < 8) sb1[t] = b1[t];
    {
        const float* fb = features + (size_t)blockIdx.x * 128 * 32;
        #pragma unroll
        for (int k = 0; k < 16; k++) {
            const int gl = k * 256 + t;
            s_f[gl >> 5][gl & 31] = fb[gl];
        }
    }
    __syncthreads();
    if (t < 32) {
        float ss = 0.f, qq = 0.f;
        #pragma unroll
        for (int w = 0; w < 8; w++) { ss += red[w][t]; qq += red[w][32 + t]; }
        const float mean = ss * (1.f / 2048.f);
        const float var  = qq * (1.f / 2048.f) - mean * mean;
        const float sc   = bn0_g[t] * rsqrtf(var + 1e-5f);
        s_sc0[t] = sc;
        s_sh0[t] = bn0_b[t] - mean * sc;
    }
    __syncthreads();

    // ---- rows (threads 0-127), h1 + partials ----
    if (t < 128) {
        float xn[32];
        #pragma unroll
        for (int c = 0; c < 32; c++) xn[c] = fmaf(s_f[t][c], s_sc0[c], s_sh0[c]);
        float h[8];
        #pragma unroll
        for (int j = 0; j < 8; j++) {
            float a = sb1[j];
            #pragma unroll
            for (int c = 0; c < 32; c++) a = fmaf(sW1[j * 32 + c], xn[c], a);
            h[j] = a;
        }
        const int row = blockIdx.x * 128 + t;
        float4* hp = (float4*)(g_h1 + row * 8);
        hp[0] = make_float4(h[0], h[1], h[2], h[3]);
        hp[1] = make_float4(h[4], h[5], h[6], h[7]);

        float sv[16];
        #pragma unroll
        for (int j = 0; j < 8; j++) { sv[j] = h[j]; sv[8 + j] = h[j] * h[j]; }
        #pragma unroll
        for (int d = 16; d; d >>= 1) {
            #pragma unroll
            for (int j = 0; j < 16; j++) sv[j] += __shfl_xor_sync(FULLMASK, sv[j], d);
        }
        if (lane < 16) s_p[warp][lane] = sv[lane];
    }
    __syncthreads();
    if (t < 16)
        g_p1[blockIdx.x][t] = s_p[0][t] + s_p[1][t] + s_p[2][t] + s_p[3][t];
}

// ============ K2: finalize bn1, h2 = relu(bn1(h1)) @ W2^T + b2, p2 partials (16 x 128) ============
__global__ __launch_bounds__(128) void k_h2(const float* __restrict__ bn1_g,
                                            const float* __restrict__ bn1_b,
                                            const float* __restrict__ W2,
                                            const float* __restrict__ b2) {
    __shared__ float sW2[64], sb2[8];
    __shared__ float s_sc1[8], s_sh1[8];
    __shared__ float s_p[4][16];
    const int t = threadIdx.x, warp = t >> 5, lane = t & 31;

    if (t < 64) sW2[t] = W2[t];
    else if (t < 72) sb2[t - 64] = b2[t - 64];
    if (t < 8) {
        float ss = 0.f, qq = 0.f;
        #pragma unroll
        for (int b = 0; b < 16; b++) { ss += g_p1[b][t]; qq += g_p1[b][8 + t]; }
        const float mean = ss * (1.f / 2048.f);
        const float var  = qq * (1.f / 2048.f) - mean * mean;
        const float sc   = bn1_g[t] * rsqrtf(var + 1e-5f);
        s_sc1[t] = sc;
        s_sh1[t] = bn1_b[t] - mean * sc;
    }
    __syncthreads();

    const int row = blockIdx.x * 128 + t;
    const float4* hp = (const float4*)(g_h1 + row * 8);
    const float4 v0 = hp[0], v1 = hp[1];
    float z[8] = {v0.x, v0.y, v0.z, v0.w, v1.x, v1.y, v1.z, v1.w};
    #pragma unroll
    for (int j = 0; j < 8; j++) z[j] = fmaxf(fmaf(z[j], s_sc1[j], s_sh1[j]), 0.f);
    float h[8];
    #pragma unroll
    for (int k = 0; k < 8; k++) {
        float a = sb2[k];
        #pragma unroll
        for (int j = 0; j < 8; j++) a = fmaf(sW2[k * 8 + j], z[j], a);
        h[k] = a;
    }
    float4* op = (float4*)(g_h2 + row * 8);
    op[0] = make_float4(h[0], h[1], h[2], h[3]);
    op[1] = make_float4(h[4], h[5], h[6], h[7]);

    float sv[16];
    #pragma unroll
    for (int j = 0; j < 8; j++) { sv[j] = h[j]; sv[8 + j] = h[j] * h[j]; }
    #pragma unroll
    for (int d = 16; d; d >>= 1) {
        #pragma unroll
        for (int j = 0; j < 16; j++) sv[j] += __shfl_xor_sync(FULLMASK, sv[j], d);
    }
    if (lane < 16) s_p[warp][lane] = sv[lane];
    __syncthreads();
    if (t < 16)
        g_p2[blockIdx.x][t] = s_p[0][t] + s_p[1][t] + s_p[2][t] + s_p[3][t];
}

// ============ K3: per-warp params preamble + R10 scan (256 x 256) ============
// Lanes 0-7 finalize bn2 & compute z; lanes 0-5 the sigmoid heads; shuffles
// broadcast. Then lane l scans steps [128l, 128l+128) in closed affine form
// (transform [[p,0],[r,p]] + offset (q1,q2)); 5-round shfl scan composes;
// butterfly reduce finishes.
__global__ __launch_bounds__(256) void k_scan(const float* __restrict__ X,
                                              const float* __restrict__ Fp,
                                              const float* __restrict__ bn2_g,
                                              const float* __restrict__ bn2_b,
                                              const float* __restrict__ W3,
                                              const float* __restrict__ b3,
                                              const float* __restrict__ pn,
                                              float* __restrict__ out) {
    const int warp = threadIdx.x >> 5, lane = threadIdx.x & 31;
    const int row = blockIdx.x * 8 + warp;
    const float cc = 0.16228221f * __ldg(Fp);   // sqrt(2^(1/3)-1)*F/pi

    // ---- per-warp params (no block sync) ----
    float zj = 0.f;
    if (lane < 8) {
        float ss = 0.f, qq = 0.f;
        #pragma unroll
        for (int b = 0; b < 16; b++) { ss += g_p2[b][lane]; qq += g_p2[b][8 + lane]; }
        const float mean = ss * (1.f / 2048.f);
        const float var  = qq * (1.f / 2048.f) - mean * mean;
        const float sc2  = __ldg(bn2_g + lane) * rsqrtf(var + 1e-5f);
        const float sh2  = __ldg(bn2_b + lane) - mean * sc2;
        zj = fmaxf(fmaf(g_h2[row * 8 + lane], sc2, sh2), 0.f);
    }
    float zz[8];
    #pragma unroll
    for (int k = 0; k < 8; k++) zz[k] = __shfl_sync(FULLMASK, zj, k);
    float sgj = 0.f;
    if (lane < 6) {
        float a = __ldg(b3 + lane) + __ldg(pn + lane);
        #pragma unroll
        for (int k = 0; k < 8; k++) a = fmaf(__ldg(W3 + lane * 8 + k), zz[k], a);
        sgj = __fdividef(1.f, 1.f + __expf(-a));
    }
    const float sg0 = __shfl_sync(FULLMASK, sgj, 0);
    const float sg1 = __shfl_sync(FULLMASK, sgj, 1);
    const float sg2 = __shfl_sync(FULLMASK, sgj, 2);
    const float sg3 = __shfl_sync(FULLMASK, sgj, 3);
    const float sg4 = __shfl_sync(FULLMASK, sgj, 4);
    const float sg5 = __shfl_sync(FULLMASK, sgj, 5);

    const float f_start = fmaf(4.5f,  sg0, 0.5f);
    const float f_inf   = fmaf(0.49f, sg1, 0.01f);
    const float f_decay = 2.f * sg2;
    const float f_T     = 2.f * sg3;
    const float w_off   = sg4;
    const float w_T     = fmaf(0.49f, sg5, 0.01f);

    const float df  = f_start - f_inf;
    const float lnD = fmaf(-2.30258509f, f_decay, -0.35667494f);  // ln(0.7*0.1^fd)
    const float H   = 10.f * __expf(-2.30258509f * f_T);          // 10*0.1^fT
    const float kf  = __fdividef(lnD, 4096.f * H);
    const float G   = __expf(kf);
    const float z0  = __fdividef(w_off, w_T);
    const float lw  = -__fdividef(1.f, 4096.f * w_T);
    const float R   = __expf(lw);

    // ---- scan (R10 body) ----
    const float* xrow = X + (size_t)row * TT;
    const int t0 = lane << 7;
    float g = __expf(kf * (float)t0);
    float e = __expf(fmaf(lw, (float)t0, z0));  // may be inf -> w = 0 (correct)
    float xp = xrow[t0 ? t0 - 1 : 0];

    float p = 1.f, r = 0.f, q1 = 0.f, q2 = 0.f;
    float a1 = 0.f, a2 = 0.f, bt = 0.f, ws = 0.f;

    const float4* xv = (const float4*)(xrow + t0);
    float4 v = __ldcs(xv);
    const float y0 = __shfl_sync(FULLMASK, v.x, 0);

#define STEP(xval) do {                               \
    float w_ = __fdividef(1.f, 1.f + e);              \
    float f_ = fmaf(df, g, f_inf);                    \
    float i_ = __fdividef(1.f, cc + f_);              \
    float b_ = f_ * i_;                               \
    float ap = fmaf(-2.f, b_, 1.f);                   \
    g *= G; e *= R;                                   \
    float m_ = fmaf(b_, ap, b_);                      \
    float xx = (xval) + xp;                           \
    float u1 = b_ * xx;                               \
    float u2 = b_ * u1;                               \
    float pm = m_ * p;                                \
    float t2 = fmaf(m_, q1, u2);                      \
    p = ap * p;                                       \
    r = fmaf(ap, r, pm);                              \
    q1 = fmaf(ap, q1, u1);                            \
    q2 = fmaf(ap, q2, t2);                            \
    a1 = fmaf(w_, r, a1);                             \
    a2 = fmaf(w_, p, a2);                             \
    bt = fmaf(w_, q2, bt);                            \
    ws += w_;                                         \
    xp = (xval);                                      \
  } while (0)

    if (lane == 0) {
        // t = 0: y2_0 = y0 passes through identity -> a2 += w0, ws += w0
        float w0 = __fdividef(1.f, 1.f + e);
        a2 = w0; ws = w0;
        g *= G; e *= R;
        // xp stays X[0] for the t=1 step
    } else {
        STEP(v.x);
    }
    STEP(v.y); STEP(v.z); STEP(v.w);
    #pragma unroll 2
    for (int i = 1; i < 32; i++) {
        v = __ldcs(xv + i);
        STEP(v.x); STEP(v.y); STEP(v.z); STEP(v.w);
    }
#undef STEP

    // inclusive scan: compose self with prefix from lower lanes
    #pragma unroll
    for (int d = 1; d < 32; d <<= 1) {
        float pL  = __shfl_up_sync(FULLMASK, p,  d);
        float rL  = __shfl_up_sync(FULLMASK, r,  d);
        float q1L = __shfl_up_sync(FULLMASK, q1, d);
        float q2L = __shfl_up_sync(FULLMASK, q2, d);
        if (lane >= d) {
            float pn2 = p * pL;
            float rn  = fmaf(r, pL, p * rL);
            float q1n = fmaf(p, q1L, q1);
            float q2n = fmaf(r, q1L, fmaf(p, q2L, q2));
            p = pn2; r = rn; q1 = q1n; q2 = q2n;
        }
    }
    // exclusive shift (identity into lane 0)
    float pe  = __shfl_up_sync(FULLMASK, p,  1);
    float re  = __shfl_up_sync(FULLMASK, r,  1);
    float q1e = __shfl_up_sync(FULLMASK, q1, 1);
    float q2e = __shfl_up_sync(FULLMASK, q2, 1);
    if (lane == 0) { pe = 1.f; re = 0.f; q1e = 0.f; q2e = 0.f; }

    const float y1i = fmaf(pe, y0, q1e);
    const float y2i = fmaf(re + pe, y0, q2e);
    float contrib = fmaf(a1, y1i, fmaf(a2, y2i, bt));

    #pragma unroll
    for (int d = 16; d; d >>= 1) {
        contrib += __shfl_xor_sync(FULLMASK, contrib, d);
        ws      += __shfl_xor_sync(FULLMASK, ws, d);
    }
    if (lane == 0) out[row] = contrib / ws;
}

extern "C" void kernel_launch(void* const* d_in, const int* in_sizes, int n_in,
                              void* d_out, int out_size) {
    const float* X        = (const float*)d_in[0];
    const float* features = (const float*)d_in[1];
    const float* F        = (const float*)d_in[2];
    const float* bn0_g    = (const float*)d_in[3];
    const float* bn0_b    = (const float*)d_in[4];
    const float* W1       = (const float*)d_in[5];
    const float* b1       = (const float*)d_in[6];
    const float* bn1_g    = (const float*)d_in[7];
    const float* bn1_b    = (const float*)d_in[8];
    const float* W2       = (const float*)d_in[9];
    const float* b2       = (const float*)d_in[10];
    const float* bn2_g    = (const float*)d_in[11];
    const float* bn2_b    = (const float*)d_in[12];
    const float* W3       = (const float*)d_in[13];
    const float* b3       = (const float*)d_in[14];
    const float* pn       = (const float*)d_in[15];
    float* out = (float*)d_out;

    k_h1<<<16, 256>>>(features, bn0_g, bn0_b, W1, b1);
    k_h2<<<16, 128>>>(bn1_g, bn1_b, W2, b2);
    k_scan<<<256, 256>>>(X, F, bn2_g, bn2_b, W3, b3, pn, out);
}